// round 17
// baseline (speedup 1.0000x reference)
#include <cuda_runtime.h>

#define NROW 512
#define DDIM 768
#define TS    16     // pair-tile side (i x j per block)
#define DC    96     // d-chunk per block
#define DCPAD 100    // padded stride: (tx*100) mod 32 hits {0,4,...,28} -> LDS.128 tiles all 32 banks
#define NCHUNK (DDIM / DC)                 // 8
#define NBLK   (32 * 32 * NCHUNK)          // 8192

__device__ float g_h1[NROW * DDIM];   // 0.5 * softmax(z1)
__device__ float g_h2[NROW * DDIM];   // 0.5 * softmax(z2)
__device__ float g_A[NROW];           // sum_d p1*ln(p1+eps) per row
__device__ float g_B[NROW];
__device__ float g_partSum[NBLK];     // per-block partial of sum_all jsd
__device__ float g_partDiag[NBLK];    // per-block partial of diag jsd
__device__ unsigned g_counter;        // last-block election (reset by softmax kernel)

__constant__ float c_eps = 1e-8f;

__device__ __forceinline__ float warp_sum(float v) {
    #pragma unroll
    for (int o = 16; o > 0; o >>= 1) v += __shfl_xor_sync(0xffffffffu, v, o);
    return v;
}
__device__ __forceinline__ double warp_sum_d(double v) {
    #pragma unroll
    for (int o = 16; o > 0; o >>= 1) v += __shfl_xor_sync(0xffffffffu, v, o);
    return v;
}
__device__ __forceinline__ float warp_max(float v) {
    #pragma unroll
    for (int o = 16; o > 0; o >>= 1) v = fmaxf(v, __shfl_xor_sync(0xffffffffu, v, o));
    return v;
}

// ---------------------------------------------------------------------------
// Kernel 1: fused row softmax for BOTH inputs (1024 blocks).
// Writes 0.5*p and per-row A_i = sum p*ln(p+eps). Resets g_counter.
// ---------------------------------------------------------------------------
__global__ __launch_bounds__(256) void softmax_fused_kernel(
    const float* __restrict__ z1, const float* __restrict__ z2) {
    __shared__ float ws[8];
    const int bid   = blockIdx.x;
    const int which = bid >> 9;
    const int row   = bid & 511;
    const int t     = threadIdx.x;
    const int warp  = t >> 5, lane = t & 31;

    const float* zr = (which ? z2 : z1) + row * DDIM;
    float* __restrict__ h = which ? g_h2 : g_h1;
    float* __restrict__ A = which ? g_B  : g_A;

    if (bid == 0 && t == 0) g_counter = 0;   // stream-ordered before pair kernel

    float zv[3];
    float mx = -3.0e38f;
    #pragma unroll
    for (int k = 0; k < 3; k++) {
        zv[k] = zr[t + k * 256];
        mx = fmaxf(mx, zv[k]);
    }
    mx = warp_max(mx);
    if (lane == 0) ws[warp] = mx;
    __syncthreads();
    mx = ws[0];
    #pragma unroll
    for (int w = 1; w < 8; w++) mx = fmaxf(mx, ws[w]);
    __syncthreads();

    float e[3];
    float s = 0.f;
    #pragma unroll
    for (int k = 0; k < 3; k++) {
        e[k] = __expf(zv[k] - mx);
        s += e[k];
    }
    s = warp_sum(s);
    if (lane == 0) ws[warp] = s;
    __syncthreads();
    s = ((ws[0] + ws[1]) + (ws[2] + ws[3])) + ((ws[4] + ws[5]) + (ws[6] + ws[7]));
    const float inv = 1.0f / s;
    __syncthreads();

    float a = 0.f;
    #pragma unroll
    for (int k = 0; k < 3; k++) {
        float p = e[k] * inv;
        a += p * __logf(p + c_eps);
        h[row * DDIM + t + k * 256] = 0.5f * p;
    }
    a = warp_sum(a);
    if (lane == 0) ws[warp] = a;
    __syncthreads();
    if (t == 0)
        A[row] = ((ws[0] + ws[1]) + (ws[2] + ws[3])) + ((ws[4] + ws[5]) + (ws[6] + ws[7]));
}

// ---------------------------------------------------------------------------
// Kernel 2: one (16x16 tile, 96-d chunk) per block; 8192 equal blocks,
// 100% occupancy (<=32 regs, 12.9KB smem -> 8 blocks/SM). Per-thread jsd
// composition: chunk-0 blocks fold in 0.5*(A_i+B_j) so all partials are
// small positive numbers (no cancellation). Last block combines scalars.
// ---------------------------------------------------------------------------
__global__ __launch_bounds__(256, 8) void pair_cross_kernel(float* __restrict__ out) {
    __shared__ float sA[TS * DCPAD];
    __shared__ float sB[TS * DCPAD];
    __shared__ float wred[16];
    __shared__ unsigned sLast;

    const int tx   = threadIdx.x;      // j within tile
    const int ty   = threadIdx.y;      // i within tile
    const int tid  = ty * 16 + tx;
    const int warp = tid >> 5, lane = tid & 31;
    const int i0   = blockIdx.y * TS;
    const int j0   = blockIdx.x * TS;
    const int c0   = blockIdx.z * DC;

    // stage this chunk: 16 rows x 24 float4 per array (3 float4/thread total)
    #pragma unroll
    for (int f = tid; f < TS * (DC / 4); f += 256) {
        const int r  = f / (DC / 4);
        const int c4 = f % (DC / 4);
        *(float4*)&sA[r * DCPAD + c4 * 4] =
            *(const float4*)&g_h1[(i0 + r) * DDIM + c0 + c4 * 4];
        *(float4*)&sB[r * DCPAD + c4 * 4] =
            *(const float4*)&g_h2[(j0 + r) * DDIM + c0 + c4 * 4];
    }
    __syncthreads();

    const float* pa = &sA[ty * DCPAD];
    const float* pb = &sB[tx * DCPAD];

    float acc0 = 0.f, acc1 = 0.f, acc2 = 0.f, acc3 = 0.f;
    #pragma unroll 8
    for (int d = 0; d < DC; d += 4) {
        float4 a = *(const float4*)&pa[d];   // broadcast: 1 LDS phase
        float4 b = *(const float4*)&pb[d];   // conflict-free: all 32 banks tiled
        float m0 = a.x + b.x;
        float m1 = a.y + b.y;
        float m2 = a.z + b.z;
        float m3 = a.w + b.w;
        acc0 = fmaf(m0, __log2f(m0 + c_eps), acc0);
        acc1 = fmaf(m1, __log2f(m1 + c_eps), acc1);
        acc2 = fmaf(m2, __log2f(m2 + c_eps), acc2);
        acc3 = fmaf(m3, __log2f(m3 + c_eps), acc3);
    }

    // per-thread jsd partial for this chunk (positive, small)
    float val = -0.69314718055994530942f * ((acc0 + acc1) + (acc2 + acc3));
    if (blockIdx.z == 0)
        val += 0.5f * (g_A[i0 + ty] + g_B[j0 + tx]);

    const float vald = (blockIdx.x == blockIdx.y && tx == ty) ? val : 0.f;
    float ws_ = warp_sum(val);
    float wd_ = warp_sum(vald);
    if (lane == 0) { wred[warp] = ws_; wred[8 + warp] = wd_; }
    __syncthreads();

    if (tid == 0) {
        float ts = 0.f, td = 0.f;
        #pragma unroll
        for (int w = 0; w < 8; w++) { ts += wred[w]; td += wred[8 + w]; }
        const int b = (blockIdx.z * gridDim.y + blockIdx.y) * gridDim.x + blockIdx.x;
        g_partSum[b]  = ts;
        g_partDiag[b] = td;
        __threadfence();
        unsigned old = atomicAdd(&g_counter, 1u);
        sLast = (old == NBLK - 1u) ? 1u : 0u;
    }
    __syncthreads();
    if (!sLast) return;

    // ---- last block: final scalar combine (deterministic order) ----
    double S = 0.0, D = 0.0;
    for (int k = tid; k < NBLK; k += 256) {
        S += (double)__ldcg(&g_partSum[k]);
        D += (double)__ldcg(&g_partDiag[k]);
    }
    S = warp_sum_d(S);
    D = warp_sum_d(D);
    __syncthreads();   // before smem scratch reuse
    __shared__ double dred[16];
    if (lane == 0) { dred[warp] = S; dred[8 + warp] = D; }
    __syncthreads();
    if (tid == 0) {
        double SS = 0.0, SD = 0.0;
        #pragma unroll
        for (int w = 0; w < 8; w++) { SS += dred[w]; SD += dred[8 + w]; }
        const double n = (double)NROW;
        const double pos = SD / n;
        const double neg = -(SS - SD) / (n * n - n);
        out[0] = (float)(pos + neg);   // LAMBD = 1.0
    }
}

// ---------------------------------------------------------------------------
extern "C" void kernel_launch(void* const* d_in, const int* in_sizes, int n_in,
                              void* d_out, int out_size) {
    const float* z1 = (const float*)d_in[0];
    const float* z2 = (const float*)d_in[1];
    float* out = (float*)d_out;

    softmax_fused_kernel<<<2 * NROW, 256>>>(z1, z2);

    dim3 grid(32, 32, NCHUNK);   // 8192 equal blocks
    dim3 block(16, 16);
    pair_cross_kernel<<<grid, block>>>(out);
}